// round 6
// baseline (speedup 1.0000x reference)
#include <cuda_runtime.h>
#include <math.h>

#define TSIG (1 << 20)
#define ALPHA_C 2000.0f
#define TAU_C 1e-7f
#define TAU2F 1e-14f
#define TOL_C 1e-6
#define NBLK 512
#define TPB 256
#define PAIRS 4              // NBLK*TPB*PAIRS == TSIG/2 exactly
#define NGRP 32
#define GSZ 16               // NGRP*GSZ == NBLK
#define SPITCH 1028
#define SMEM_FFT ((8 * SPITCH + 512) * (int)sizeof(float2))
#define SMEM_PERSIST (2 * 1024 * (int)sizeof(float4))   // F slice + prev-lam slice

// Scratch:
// [0,T)    : F (forward FFT of x)
// [T,2T)   : final lambda (written by persist kernel)
// [2T,5T)  : FFT work (forward pass1 out; inverse pass1 out, 3 modes)
__device__ float2 g_buf[5 * (size_t)TSIG];
__device__ float  g_part[2][NBLK][8];
__device__ float  g_part2[2][NGRP][8];
__device__ int    g_flag[NBLK];
__device__ int    g_flag2[NGRP];
__device__ unsigned g_gen;
__device__ float  g_wout[2][4];     // w0,w1,w2,convflag
__device__ float  g_omega_out[3];

__device__ __forceinline__ float2 cmulf(float2 a, float2 b) {
    return make_float2(a.x * b.x - a.y * b.y, a.x * b.y + a.y * b.x);
}

// ---------------------------------------------------------------------------
// Four-step FFT, N = 1024 x 1024 (unchanged).
// ---------------------------------------------------------------------------

__device__ __forceinline__ void fft1024_shared(float2*& src, float2*& dst,
                                               const float2* tw, int t) {
    #pragma unroll 1
    for (int s = 0; s < 10; s++) {
        int r = 1 << s;
        #pragma unroll
        for (int u = 0; u < 8; u++) {
            int id = u * 256 + t;
            int c  = id >> 9;
            int bf = id & 511;
            int j  = bf >> s;
            float2 a = src[c * SPITCH + bf];
            float2 b = src[c * SPITCH + bf + 512];
            float2 w = tw[j << s];
            int o = bf + ((bf >> s) << s);
            dst[c * SPITCH + o]     = make_float2(a.x + b.x, a.y + b.y);
            float2 d = make_float2(a.x - b.x, a.y - b.y);
            dst[c * SPITCH + o + r] = cmulf(d, w);
        }
        __syncthreads();
        float2* tmp = src; src = dst; dst = tmp;
    }
}

__device__ __forceinline__ void build_tw(float2* tw, int t) {
    for (int m = t; m < 512; m += 256) {
        float s, c;
        sincospif((float)m * (1.0f / 512.0f), &s, &c);
        tw[m] = make_float2(c, -s);
    }
}

// MODE 0: real input x.  MODE 1: fused conj(u_hat) from (F, lam, omega_out).
template <int MODE>
__global__ void __launch_bounds__(256) fft_pass1(const float* rin, float2* out) {
    extern __shared__ float2 sh[];
    float2* bufA = sh;
    float2* bufB = sh + 4 * SPITCH;
    float2* tw   = sh + 8 * SPITCH;
    const int t   = threadIdx.x;
    const int n2b = blockIdx.x * 4;
    const int b   = blockIdx.y;

    build_tw(tw, t);

    float w0 = 0.f, w1 = 0.f, w2 = 0.f;
    const float2* __restrict__ F   = g_buf;
    const float2* __restrict__ lam = g_buf + (size_t)TSIG;
    if (MODE == 1) { w0 = g_omega_out[0]; w1 = g_omega_out[1]; w2 = g_omega_out[2]; }
    const float invT = 1.0f / (float)TSIG;

    for (int i = t; i < 4096; i += 256) {
        int n1 = i >> 2, c = i & 3;
        int j = (n1 << 10) + n2b + c;
        float2 v;
        if (MODE == 0) {
            v = make_float2(rin[j], 0.0f);
        } else {
            float f = (float)j * invT;
            if (j >= TSIG / 2) f -= 1.0f;
            float2 Fv = F[j];
            float2 Lv = lam[j];
            float rr = Fv.x - 0.5f * Lv.x;
            float ri = Fv.y - 0.5f * Lv.y;
            float d0 = f - w0, d1 = f - w1, d2 = f - w2;
            float b0 = d0 * d0, b1 = d1 * d1, b2 = d2 * d2;
            float sum = (b == 0) ? (b0 + b1) : (b == 1) ? (b0 + b1 + b2) : (b1 + b2);
            float iv = __fdividef(1.0f, fmaf(ALPHA_C, sum + TAU2F, 1.0f));
            v = make_float2(rr * iv, -(ri * iv));   // conj(u_hat)
        }
        bufA[c * SPITCH + n1] = v;
    }
    __syncthreads();

    float2 *src = bufA, *dst = bufB;
    fft1024_shared(src, dst, tw, t);

    for (int i = t; i < 4096; i += 256) {
        int k1 = i >> 2, c = i & 3;
        int n2 = n2b + c;
        int m = n2 * k1;
        float s, cth;
        sincospif((float)m * (1.0f / 524288.0f), &s, &cth);
        float2 v = src[c * SPITCH + k1];
        out[(size_t)b * TSIG + ((size_t)k1 << 10) + n2] =
            cmulf(v, make_float2(cth, -s));
    }
}

template <int REAL_OUT>
__global__ void __launch_bounds__(256) fft_pass2(const float2* in, float2* cout,
                                                 float* rout) {
    extern __shared__ float2 sh[];
    float2* bufA = sh;
    float2* bufB = sh + 4 * SPITCH;
    float2* tw   = sh + 8 * SPITCH;
    const int t   = threadIdx.x;
    const int k1b = blockIdx.x * 4;
    const int b   = blockIdx.y;

    build_tw(tw, t);
    for (int i = t; i < 4096; i += 256) {
        int c = i >> 10, n2 = i & 1023;
        bufA[c * SPITCH + n2] = in[(size_t)b * TSIG + ((size_t)(k1b + c) << 10) + n2];
    }
    __syncthreads();

    float2 *src = bufA, *dst = bufB;
    fft1024_shared(src, dst, tw, t);

    const float invT = 1.0f / (float)TSIG;
    for (int i = t; i < 4096; i += 256) {
        int k2 = i >> 2, c = i & 3;
        float2 v = src[c * SPITCH + k2];
        size_t o = (size_t)b * TSIG + ((size_t)k2 << 10) + k1b + c;
        if (REAL_OUT) rout[o] = v.x * invT;
        else          cout[o] = v;
    }
}

// ---------------------------------------------------------------------------
// Persistent VMD: lambda in registers, F in smem.
// Tree barrier: per-block flags -> 32 aggregators -> block 0 -> single gen flag.
// No atomics; only ~560 threads ever poll global memory.
// ---------------------------------------------------------------------------

__global__ void reset_flags() {
    int i = threadIdx.x;
    if (i < NBLK) g_flag[i] = 0;
    if (i < NGRP) g_flag2[i] = 0;
    if (i == 0) g_gen = 0;
}

__device__ __forceinline__ void inv3(float b0, float b1, float b2,
                                     float& i0, float& i1, float& i2) {
    float a = fmaf(ALPHA_C, b0 + b1 + TAU2F, 1.0f);
    float b = fmaf(ALPHA_C, b2, a);
    float c = fmaf(ALPHA_C, b1 + b2 + TAU2F, 1.0f);
    float inv = __fdividef(1.0f, a * b * c);
    i0 = inv * (b * c);
    i1 = inv * (a * c);
    i2 = inv * (a * b);
}

__global__ void __launch_bounds__(TPB, 4) vmd_persist(const float* om_init) {
    extern __shared__ float4 shp[];
    float4* shF    = shp;          // [0,1024): F slice
    float4* shPrev = shp + 1024;   // [1024,2048): lam_{n-1} saved at n%10==9
    __shared__ float sred[8][8];
    __shared__ float swnew[4];     // w0,w1,w2,conv

    const int tix = threadIdx.x, blk = blockIdx.x;
    const int lane = tix & 31, warp = tix >> 5;
    const float invT = 1.0f / (float)TSIG;
    const float foff = (blk >= NBLK / 2) ? 1.0f : 0.0f;

    const float4* __restrict__ F4 = reinterpret_cast<const float4*>(g_buf);
    float4* lamG = reinterpret_cast<float4*>(g_buf + (size_t)TSIG);

    float4 lam[PAIRS];
    #pragma unroll
    for (int k = 0; k < PAIRS; k++) {
        int p = blk * 1024 + k * 256 + tix;
        shF[k * 256 + tix] = F4[p];
        lam[k] = make_float4(0.f, 0.f, 0.f, 0.f);
    }
    float w0 = om_init[0], w1 = om_init[1], w2 = om_init[2];
    float v0 = 0.f, v1 = 0.f, v2 = 0.f;   // omega_{n-1} snapshot for check
    bool converged = false;
    __syncthreads();

    for (int n = 0; n <= 48; n++) {
        const int par = n & 1;
        const bool is_check  = (n > 0) && (n % 10 == 0);
        const bool save_prev = (n % 10 == 9);
        float acc[8] = {0, 0, 0, 0, 0, 0, 0, 0};

        #pragma unroll
        for (int k = 0; k < PAIRS; k++) {
            int p = blk * 1024 + k * 256 + tix;
            float f0 = (float)(p << 1) * invT - foff;
            float f1 = f0 + invT;
            float4 Fv = shF[k * 256 + tix];
            float4 L  = lam[k];
            if (save_prev) shPrev[k * 256 + tix] = L;     // lam_{n-1} for check
            if (is_check)  lamG[p] = L;                   // freeze-source lam_{n-1}
            float4 Lold;
            if (is_check)  Lold = shPrev[k * 256 + tix];  // lam_{n-2}
            float4 Lnew;

            #pragma unroll
            for (int e = 0; e < 2; e++) {
                float f  = e ? f1 : f0;
                float Fr = e ? Fv.z : Fv.x, Fi = e ? Fv.w : Fv.y;
                float Lr = e ? L.z  : L.x,  Li = e ? L.w  : L.y;
                float rr = fmaf(-0.5f, Lr, Fr);
                float ri = fmaf(-0.5f, Li, Fi);
                float d0 = f - w0, d1 = f - w1, d2 = f - w2;
                float i0, i1, i2;
                inv3(d0 * d0, d1 * d1, d2 * d2, i0, i1, i2);
                float mag = rr * rr + ri * ri;
                float pw0 = mag * i0 * i0, pw1 = mag * i1 * i1, pw2 = mag * i2 * i2;
                acc[0] += pw0; acc[1] += pw1; acc[2] += pw2;
                acc[3] = fmaf(f, pw0, acc[3]);
                acc[4] = fmaf(f, pw1, acc[4]);
                acc[5] = fmaf(f, pw2, acc[5]);
                float isum = i0 + i1 + i2;
                float lr = fmaf(TAU_C, fmaf(rr, isum, -Fr), Lr);
                float li = fmaf(TAU_C, fmaf(ri, isum, -Fi), Li);
                if (e) { Lnew.z = lr; Lnew.w = li; } else { Lnew.x = lr; Lnew.y = li; }

                if (is_check) {
                    float Pr = e ? Lold.z : Lold.x, Pi = e ? Lold.w : Lold.y;
                    float qr = fmaf(-0.5f, Pr, Fr);
                    float qi = fmaf(-0.5f, Pi, Fi);
                    float e0 = f - v0, e1 = f - v1, e2 = f - v2;
                    float h0, h1, h2;
                    inv3(e0 * e0, e1 * e1, e2 * e2, h0, h1, h2);
                    float qmag = qr * qr + qi * qi;
                    acc[7] += qmag * (h0 * h0 + h1 * h1 + h2 * h2);
                    float xr, xi;
                    xr = rr * i0 - qr * h0; xi = ri * i0 - qi * h0; acc[6] += xr * xr + xi * xi;
                    xr = rr * i1 - qr * h1; xi = ri * i1 - qi * h1; acc[6] += xr * xr + xi * xi;
                    xr = rr * i2 - qr * h2; xi = ri * i2 - qi * h2; acc[6] += xr * xr + xi * xi;
                }
            }
            lam[k] = Lnew;
        }

        // block tree-reduce 8 partials
        #pragma unroll
        for (int a = 0; a < 8; a++) {
            float v = acc[a];
            #pragma unroll
            for (int o = 16; o; o >>= 1) v += __shfl_down_sync(0xffffffffu, v, o);
            if (lane == 0) sred[warp][a] = v;
        }
        __syncthreads();

        // L0 publish: thread0 writes partials + per-block flag (distinct addrs)
        if (tix == 0) {
            float s[8];
            #pragma unroll
            for (int a = 0; a < 8; a++) {
                float v = 0;
                #pragma unroll
                for (int w = 0; w < 8; w++) v += sred[w][a];
                s[a] = v;
            }
            float4* dst = reinterpret_cast<float4*>(&g_part[par][blk][0]);
            dst[0] = make_float4(s[0], s[1], s[2], s[3]);
            dst[1] = make_float4(s[4], s[5], s[6], s[7]);
            __threadfence();
            *((volatile int*)&g_flag[blk]) = n + 1;
        }

        // L1: aggregator blocks (blk < 32), warp 0 only
        if (blk < NGRP && warp == 0) {
            if (lane < GSZ) {
                volatile int* fl = g_flag;
                while (fl[blk * GSZ + lane] < n + 1) __nanosleep(40);
            }
            __syncwarp();
            __threadfence();
            float s[8] = {0, 0, 0, 0, 0, 0, 0, 0};
            if (lane < GSZ) {
                const volatile float* P = &g_part[par][blk * GSZ + lane][0];
                #pragma unroll
                for (int a = 0; a < 8; a++) s[a] = P[a];
            }
            #pragma unroll
            for (int a = 0; a < 8; a++) {
                #pragma unroll
                for (int o = 8; o; o >>= 1)
                    s[a] += __shfl_down_sync(0xffffffffu, s[a], o);
            }
            if (lane == 0) {
                float4* dst2 = reinterpret_cast<float4*>(&g_part2[par][blk][0]);
                dst2[0] = make_float4(s[0], s[1], s[2], s[3]);
                dst2[1] = make_float4(s[4], s[5], s[6], s[7]);
                __threadfence();
                *((volatile int*)&g_flag2[blk]) = n + 1;
            }
        }

        // L2: block 0 warp 0 reduces 32 group partials in fp64, publishes omega
        if (blk == 0 && warp == 0) {
            {
                volatile int* fl2 = g_flag2;
                while (fl2[lane] < n + 1) __nanosleep(40);
            }
            __syncwarp();
            __threadfence();
            double sd[8];
            const volatile float* P2 = &g_part2[par][lane][0];
            #pragma unroll
            for (int a = 0; a < 8; a++) sd[a] = (double)P2[a];
            #pragma unroll
            for (int a = 0; a < 8; a++) {
                #pragma unroll
                for (int o = 16; o; o >>= 1)
                    sd[a] += __shfl_down_sync(0xffffffffu, sd[a], o);
            }
            if (lane == 0) {
                double wn0 = sd[3] / sd[0], wn1 = sd[4] / sd[1], wn2 = sd[5] / sd[2];
                float convf = 0.f;
                if (is_check) {
                    double udiff = sd[6] / sd[7];
                    double omd = (fabs(wn0 - wn2) + fabs(wn1 - wn0) + fabs(wn2 - wn1)) * (1.0 / 3.0);
                    if (udiff < TOL_C && omd < TOL_C) convf = 1.f;
                }
                volatile float* W = &g_wout[par][0];
                W[0] = (float)wn0; W[1] = (float)wn1; W[2] = (float)wn2; W[3] = convf;
                __threadfence();
                *((volatile unsigned*)&g_gen) = (unsigned)(n + 1);
            }
        }

        // L3: every block's thread0 polls the single gen flag, broadcasts
        if (tix == 0) {
            volatile unsigned* vg = &g_gen;
            while (*vg < (unsigned)(n + 1)) __nanosleep(60);
            __threadfence();
            const volatile float* W = &g_wout[par][0];
            swnew[0] = W[0]; swnew[1] = W[1]; swnew[2] = W[2]; swnew[3] = W[3];
        }
        __syncthreads();

        if (swnew[3] != 0.f) { converged = true; break; }  // frozen omega = w
        v0 = w0; v1 = w1; v2 = w2;
        w0 = swnew[0]; w1 = swnew[1]; w2 = swnew[2];
        __syncthreads();                                   // protect swnew reuse
    }

    // write final lambda (frozen case already written during the check sweep)
    if (!converged) {
        #pragma unroll
        for (int k = 0; k < PAIRS; k++)
            lamG[blk * 1024 + k * 256 + tix] = lam[k];
        if (tix == 0 && blk == 0) {
            g_omega_out[0] = swnew[0]; g_omega_out[1] = swnew[1]; g_omega_out[2] = swnew[2];
        }
    } else {
        if (tix == 0 && blk == 0) {
            g_omega_out[0] = w0; g_omega_out[1] = w1; g_omega_out[2] = w2;
        }
    }
}

// ---------------------------------------------------------------------------

extern "C" void kernel_launch(void* const* d_in, const int* in_sizes, int n_in,
                              void* d_out, int out_size) {
    const float* x       = (const float*)d_in[0];
    const float* om_init = (const float*)d_in[1];
    float* out = (float*)d_out;

    cudaFuncSetAttribute(fft_pass1<0>, cudaFuncAttributeMaxDynamicSharedMemorySize, SMEM_FFT);
    cudaFuncSetAttribute(fft_pass1<1>, cudaFuncAttributeMaxDynamicSharedMemorySize, SMEM_FFT);
    cudaFuncSetAttribute(fft_pass2<0>, cudaFuncAttributeMaxDynamicSharedMemorySize, SMEM_FFT);
    cudaFuncSetAttribute(fft_pass2<1>, cudaFuncAttributeMaxDynamicSharedMemorySize, SMEM_FFT);
    cudaFuncSetAttribute(vmd_persist,  cudaFuncAttributeMaxDynamicSharedMemorySize, SMEM_PERSIST);

    float2* buf;
    cudaGetSymbolAddress((void**)&buf, g_buf);
    float2* F  = buf;                       // [0, T)
    float2* wk = buf + (size_t)2 * TSIG;    // FFT work region (3T)

    // Forward FFT of x -> F
    fft_pass1<0><<<dim3(256, 1), 256, SMEM_FFT>>>(x, wk);
    fft_pass2<0><<<dim3(256, 1), 256, SMEM_FFT>>>(wk, F, nullptr);

    reset_flags<<<1, 512>>>();
    vmd_persist<<<NBLK, TPB, SMEM_PERSIST>>>(om_init);

    // inverse: pass1 computes conj(u_hat) on the fly, then Re(fft(conj(u)))/T
    fft_pass1<1><<<dim3(256, 3), 256, SMEM_FFT>>>(nullptr, wk);
    fft_pass2<1><<<dim3(256, 3), 256, SMEM_FFT>>>(wk, nullptr, out);
}

// round 7
// speedup vs baseline: 2.0626x; 2.0626x over previous
#include <cuda_runtime.h>
#include <math.h>

#define TSIG (1 << 20)
#define ALPHA_C 2000.0f
#define TAU_C 1e-7f
#define TAU2F 1e-14f
#define TOL_C 1e-6
#define NBLK 256
#define TPB 256
#define PAIRS 8              // NBLK*TPB*PAIRS == TSIG/2 exactly
#define SPITCH 1028
#define SMEM_FFT ((8 * SPITCH + 512) * (int)sizeof(float2))
#define SMEM_PERSIST (3 * 2048 * (int)sizeof(float4))   // F + lam + prev-lam slices

// Scratch:
// [0,T)    : F (forward FFT of x)
// [T,2T)   : final lambda (written by persist kernel)
// [2T,5T)  : FFT work (forward pass1 out; inverse pass1 out, 3 modes)
__device__ float2 g_buf[5 * (size_t)TSIG];
__device__ float  g_part[2][NBLK][8];
__device__ int    g_flag[NBLK];
__device__ unsigned g_gen;
__device__ float  g_wout[2][4];     // w0,w1,w2,convflag
__device__ float  g_omega_out[3];

__device__ __forceinline__ float2 cmulf(float2 a, float2 b) {
    return make_float2(a.x * b.x - a.y * b.y, a.x * b.y + a.y * b.x);
}

// ---------------------------------------------------------------------------
// Four-step FFT, N = 1024 x 1024 (unchanged from R6).
// ---------------------------------------------------------------------------

__device__ __forceinline__ void fft1024_shared(float2*& src, float2*& dst,
                                               const float2* tw, int t) {
    #pragma unroll 1
    for (int s = 0; s < 10; s++) {
        int r = 1 << s;
        #pragma unroll
        for (int u = 0; u < 8; u++) {
            int id = u * 256 + t;
            int c  = id >> 9;
            int bf = id & 511;
            int j  = bf >> s;
            float2 a = src[c * SPITCH + bf];
            float2 b = src[c * SPITCH + bf + 512];
            float2 w = tw[j << s];
            int o = bf + ((bf >> s) << s);
            dst[c * SPITCH + o]     = make_float2(a.x + b.x, a.y + b.y);
            float2 d = make_float2(a.x - b.x, a.y - b.y);
            dst[c * SPITCH + o + r] = cmulf(d, w);
        }
        __syncthreads();
        float2* tmp = src; src = dst; dst = tmp;
    }
}

__device__ __forceinline__ void build_tw(float2* tw, int t) {
    for (int m = t; m < 512; m += 256) {
        float s, c;
        sincospif((float)m * (1.0f / 512.0f), &s, &c);
        tw[m] = make_float2(c, -s);
    }
}

// MODE 0: real input x.  MODE 1: fused conj(u_hat) from (F, lam, omega_out).
template <int MODE>
__global__ void __launch_bounds__(256) fft_pass1(const float* rin, float2* out) {
    extern __shared__ float2 sh[];
    float2* bufA = sh;
    float2* bufB = sh + 4 * SPITCH;
    float2* tw   = sh + 8 * SPITCH;
    const int t   = threadIdx.x;
    const int n2b = blockIdx.x * 4;
    const int b   = blockIdx.y;

    build_tw(tw, t);

    float w0 = 0.f, w1 = 0.f, w2 = 0.f;
    const float2* __restrict__ F   = g_buf;
    const float2* __restrict__ lam = g_buf + (size_t)TSIG;
    if (MODE == 1) { w0 = g_omega_out[0]; w1 = g_omega_out[1]; w2 = g_omega_out[2]; }
    const float invT = 1.0f / (float)TSIG;

    for (int i = t; i < 4096; i += 256) {
        int n1 = i >> 2, c = i & 3;
        int j = (n1 << 10) + n2b + c;
        float2 v;
        if (MODE == 0) {
            v = make_float2(rin[j], 0.0f);
        } else {
            float f = (float)j * invT;
            if (j >= TSIG / 2) f -= 1.0f;
            float2 Fv = F[j];
            float2 Lv = lam[j];
            float rr = Fv.x - 0.5f * Lv.x;
            float ri = Fv.y - 0.5f * Lv.y;
            float d0 = f - w0, d1 = f - w1, d2 = f - w2;
            float b0 = d0 * d0, b1 = d1 * d1, b2 = d2 * d2;
            float sum = (b == 0) ? (b0 + b1) : (b == 1) ? (b0 + b1 + b2) : (b1 + b2);
            float iv = __fdividef(1.0f, fmaf(ALPHA_C, sum + TAU2F, 1.0f));
            v = make_float2(rr * iv, -(ri * iv));   // conj(u_hat)
        }
        bufA[c * SPITCH + n1] = v;
    }
    __syncthreads();

    float2 *src = bufA, *dst = bufB;
    fft1024_shared(src, dst, tw, t);

    for (int i = t; i < 4096; i += 256) {
        int k1 = i >> 2, c = i & 3;
        int n2 = n2b + c;
        int m = n2 * k1;
        float s, cth;
        sincospif((float)m * (1.0f / 524288.0f), &s, &cth);
        float2 v = src[c * SPITCH + k1];
        out[(size_t)b * TSIG + ((size_t)k1 << 10) + n2] =
            cmulf(v, make_float2(cth, -s));
    }
}

template <int REAL_OUT>
__global__ void __launch_bounds__(256) fft_pass2(const float2* in, float2* cout,
                                                 float* rout) {
    extern __shared__ float2 sh[];
    float2* bufA = sh;
    float2* bufB = sh + 4 * SPITCH;
    float2* tw   = sh + 8 * SPITCH;
    const int t   = threadIdx.x;
    const int k1b = blockIdx.x * 4;
    const int b   = blockIdx.y;

    build_tw(tw, t);
    for (int i = t; i < 4096; i += 256) {
        int c = i >> 10, n2 = i & 1023;
        bufA[c * SPITCH + n2] = in[(size_t)b * TSIG + ((size_t)(k1b + c) << 10) + n2];
    }
    __syncthreads();

    float2 *src = bufA, *dst = bufB;
    fft1024_shared(src, dst, tw, t);

    const float invT = 1.0f / (float)TSIG;
    for (int i = t; i < 4096; i += 256) {
        int k2 = i >> 2, c = i & 3;
        float2 v = src[c * SPITCH + k2];
        size_t o = (size_t)b * TSIG + ((size_t)k2 << 10) + k1b + c;
        if (REAL_OUT) rout[o] = v.x * invT;
        else          cout[o] = v;
    }
}

// ---------------------------------------------------------------------------
// Persistent VMD. F and lambda live in SMEM (no register pressure, no global
// streaming). Flat barrier: 256 per-block flags -> block0 reduces -> 1 release.
// ---------------------------------------------------------------------------

__global__ void reset_flags() {
    int i = threadIdx.x;
    if (i < NBLK) g_flag[i] = 0;
    if (i == 0) g_gen = 0;
}

__global__ void __launch_bounds__(TPB, 2) vmd_persist(const float* om_init) {
    extern __shared__ float4 shp[];
    float4* shF = shp;          // [0,2048)
    float4* shL = shp + 2048;   // [2048,4096): lambda state
    float4* shP = shp + 4096;   // [4096,6144): lam saved at n%10==9
    __shared__ float  sred[8][8];
    __shared__ double dsum[8][8];
    __shared__ double dfin[8];
    __shared__ float  swnew[4];

    const int tix = threadIdx.x, blk = blockIdx.x;
    const int lane = tix & 31, warp = tix >> 5;
    const float invT = 1.0f / (float)TSIG;
    const float foff = (blk >= NBLK / 2) ? 1.0f : 0.0f;

    const float4* __restrict__ F4 = reinterpret_cast<const float4*>(g_buf);
    float4* lamG = reinterpret_cast<float4*>(g_buf + (size_t)TSIG);

    #pragma unroll
    for (int k = 0; k < PAIRS; k++) {
        int idx = k * 256 + tix;
        shF[idx] = F4[blk * 2048 + idx];
        shL[idx] = make_float4(0.f, 0.f, 0.f, 0.f);
    }
    float w0 = om_init[0], w1 = om_init[1], w2 = om_init[2];
    float v0 = 0.f, v1 = 0.f, v2 = 0.f;   // omega entering previous iteration
    bool converged = false;
    __syncthreads();

    for (int n = 0; n <= 48; n++) {
        const int par = n & 1;
        const bool is_check  = (n > 0) && (n % 10 == 0);
        const bool save_prev = (n % 10 == 9);
        float acc[8] = {0, 0, 0, 0, 0, 0, 0, 0};

        #pragma unroll 2
        for (int k = 0; k < PAIRS; k++) {
            int idx = k * 256 + tix;
            int p   = blk * 2048 + idx;
            float f0 = (float)(p << 1) * invT - foff;
            float f1 = f0 + invT;
            float4 Fv = shF[idx];
            float4 L  = shL[idx];
            if (save_prev) shP[idx] = L;     // lam entering iteration n+1's check
            if (is_check)  lamG[p] = L;      // freeze-source lam (entering check)
            float4 Lold;
            if (is_check)  Lold = shP[idx];
            float4 Lnew;

            #pragma unroll
            for (int e = 0; e < 2; e++) {
                float f  = e ? f1 : f0;
                float Fr = e ? Fv.z : Fv.x, Fi = e ? Fv.w : Fv.y;
                float Lr = e ? L.z  : L.x,  Li = e ? L.w  : L.y;
                float rr = fmaf(-0.5f, Lr, Fr);
                float ri = fmaf(-0.5f, Li, Fi);
                float d0 = f - w0, d1 = f - w1, d2 = f - w2;
                float b0 = d0 * d0, b1 = d1 * d1, b2 = d2 * d2;
                float t01 = b0 + b1 + TAU2F, t12 = b1 + b2 + TAU2F;
                float i0 = __fdividef(1.0f, fmaf(ALPHA_C, t01, 1.0f));
                float i1 = __fdividef(1.0f, fmaf(ALPHA_C, t01 + b2, 1.0f));
                float i2 = __fdividef(1.0f, fmaf(ALPHA_C, t12, 1.0f));
                float mag = fmaf(rr, rr, ri * ri);
                float pw0 = mag * i0 * i0, pw1 = mag * i1 * i1, pw2 = mag * i2 * i2;
                acc[0] += pw0; acc[1] += pw1; acc[2] += pw2;
                acc[3] = fmaf(f, pw0, acc[3]);
                acc[4] = fmaf(f, pw1, acc[4]);
                acc[5] = fmaf(f, pw2, acc[5]);
                float isum = i0 + i1 + i2;
                float lr = fmaf(TAU_C, fmaf(rr, isum, -Fr), Lr);
                float li = fmaf(TAU_C, fmaf(ri, isum, -Fi), Li);
                if (e) { Lnew.z = lr; Lnew.w = li; } else { Lnew.x = lr; Lnew.y = li; }

                if (is_check) {
                    float Pr = e ? Lold.z : Lold.x, Pi = e ? Lold.w : Lold.y;
                    float qr = fmaf(-0.5f, Pr, Fr);
                    float qi = fmaf(-0.5f, Pi, Fi);
                    float e0 = f - v0, e1 = f - v1, e2 = f - v2;
                    float c0 = e0 * e0, c1 = e1 * e1, c2 = e2 * e2;
                    float s01 = c0 + c1 + TAU2F, s12 = c1 + c2 + TAU2F;
                    float h0 = __fdividef(1.0f, fmaf(ALPHA_C, s01, 1.0f));
                    float h1 = __fdividef(1.0f, fmaf(ALPHA_C, s01 + c2, 1.0f));
                    float h2 = __fdividef(1.0f, fmaf(ALPHA_C, s12, 1.0f));
                    float qmag = fmaf(qr, qr, qi * qi);
                    acc[7] += qmag * (h0 * h0 + h1 * h1 + h2 * h2);
                    float xr, xi;
                    xr = rr * i0 - qr * h0; xi = ri * i0 - qi * h0; acc[6] += xr * xr + xi * xi;
                    xr = rr * i1 - qr * h1; xi = ri * i1 - qi * h1; acc[6] += xr * xr + xi * xi;
                    xr = rr * i2 - qr * h2; xi = ri * i2 - qi * h2; acc[6] += xr * xr + xi * xi;
                }
            }
            shL[idx] = Lnew;
        }

        // block tree-reduce 8 partials
        #pragma unroll
        for (int a = 0; a < 8; a++) {
            float v = acc[a];
            #pragma unroll
            for (int o = 16; o; o >>= 1) v += __shfl_down_sync(0xffffffffu, v, o);
            if (lane == 0) sred[warp][a] = v;
        }
        __syncthreads();

        // publish partials + flag (distinct addresses per block)
        if (tix == 0) {
            float s[8];
            #pragma unroll
            for (int a = 0; a < 8; a++) {
                float v = 0;
                #pragma unroll
                for (int w = 0; w < 8; w++) v += sred[w][a];
                s[a] = v;
            }
            float4* dst = reinterpret_cast<float4*>(&g_part[par][blk][0]);
            dst[0] = make_float4(s[0], s[1], s[2], s[3]);
            dst[1] = make_float4(s[4], s[5], s[6], s[7]);
            __threadfence();
            *((volatile int*)&g_flag[blk]) = n + 1;
        }

        // block 0 gathers all 256 partials (1 flag per thread), reduces in fp64
        if (blk == 0) {
            {
                volatile int* fl = g_flag;
                while (fl[tix] < n + 1) __nanosleep(32);
            }
            __threadfence();
            __syncthreads();
            double d[8];
            {
                const volatile float* P = &g_part[par][tix][0];
                #pragma unroll
                for (int a = 0; a < 8; a++) d[a] = (double)P[a];
            }
            #pragma unroll
            for (int a = 0; a < 8; a++) {
                #pragma unroll
                for (int o = 16; o; o >>= 1)
                    d[a] += __shfl_down_sync(0xffffffffu, d[a], o);
                if (lane == 0) dsum[warp][a] = d[a];
            }
            __syncthreads();
            if (tix < 8) {
                double v = 0;
                #pragma unroll
                for (int w = 0; w < 8; w++) v += dsum[w][tix];
                dfin[tix] = v;
            }
            __syncthreads();
            if (tix == 0) {
                double wn0 = dfin[3] / dfin[0], wn1 = dfin[4] / dfin[1], wn2 = dfin[5] / dfin[2];
                float convf = 0.f;
                if (is_check) {
                    double udiff = dfin[6] / dfin[7];
                    double omd = (fabs(wn0 - wn2) + fabs(wn1 - wn0) + fabs(wn2 - wn1)) * (1.0 / 3.0);
                    if (udiff < TOL_C && omd < TOL_C) convf = 1.f;
                }
                volatile float* W = &g_wout[par][0];
                W[0] = (float)wn0; W[1] = (float)wn1; W[2] = (float)wn2; W[3] = convf;
                __threadfence();
                *((volatile unsigned*)&g_gen) = (unsigned)(n + 1);
            }
        }

        // all blocks: thread0 polls the single release line, broadcasts via smem
        if (tix == 0) {
            volatile unsigned* vg = &g_gen;
            while (*vg < (unsigned)(n + 1)) __nanosleep(32);
            __threadfence();
            const volatile float* W = &g_wout[par][0];
            swnew[0] = W[0]; swnew[1] = W[1]; swnew[2] = W[2]; swnew[3] = W[3];
        }
        __syncthreads();

        float nw0 = swnew[0], nw1 = swnew[1], nw2 = swnew[2], cf = swnew[3];
        __syncthreads();                         // protect swnew before next iter
        if (cf != 0.f) { converged = true; break; }   // frozen omega = w
        v0 = w0; v1 = w1; v2 = w2;
        w0 = nw0; w1 = nw1; w2 = nw2;
    }

    // final lambda + omega (frozen case: lamG already written at the check sweep)
    if (!converged) {
        #pragma unroll
        for (int k = 0; k < PAIRS; k++) {
            int idx = k * 256 + tix;
            lamG[blk * 2048 + idx] = shL[idx];
        }
        if (tix == 0 && blk == 0) {
            g_omega_out[0] = swnew[0]; g_omega_out[1] = swnew[1]; g_omega_out[2] = swnew[2];
        }
    } else {
        if (tix == 0 && blk == 0) {
            g_omega_out[0] = w0; g_omega_out[1] = w1; g_omega_out[2] = w2;
        }
    }
}

// ---------------------------------------------------------------------------

extern "C" void kernel_launch(void* const* d_in, const int* in_sizes, int n_in,
                              void* d_out, int out_size) {
    const float* x       = (const float*)d_in[0];
    const float* om_init = (const float*)d_in[1];
    float* out = (float*)d_out;

    cudaFuncSetAttribute(fft_pass1<0>, cudaFuncAttributeMaxDynamicSharedMemorySize, SMEM_FFT);
    cudaFuncSetAttribute(fft_pass1<1>, cudaFuncAttributeMaxDynamicSharedMemorySize, SMEM_FFT);
    cudaFuncSetAttribute(fft_pass2<0>, cudaFuncAttributeMaxDynamicSharedMemorySize, SMEM_FFT);
    cudaFuncSetAttribute(fft_pass2<1>, cudaFuncAttributeMaxDynamicSharedMemorySize, SMEM_FFT);
    cudaFuncSetAttribute(vmd_persist,  cudaFuncAttributeMaxDynamicSharedMemorySize, SMEM_PERSIST);

    float2* buf;
    cudaGetSymbolAddress((void**)&buf, g_buf);
    float2* F  = buf;                       // [0, T)
    float2* wk = buf + (size_t)2 * TSIG;    // FFT work region (3T)

    // Forward FFT of x -> F
    fft_pass1<0><<<dim3(256, 1), 256, SMEM_FFT>>>(x, wk);
    fft_pass2<0><<<dim3(256, 1), 256, SMEM_FFT>>>(wk, F, nullptr);

    reset_flags<<<1, 256>>>();
    vmd_persist<<<NBLK, TPB, SMEM_PERSIST>>>(om_init);

    // inverse: pass1 computes conj(u_hat) on the fly, then Re(fft(conj(u)))/T
    fft_pass1<1><<<dim3(256, 3), 256, SMEM_FFT>>>(nullptr, wk);
    fft_pass2<1><<<dim3(256, 3), 256, SMEM_FFT>>>(wk, nullptr, out);
}